// round 5
// baseline (speedup 1.0000x reference)
#include <cuda_runtime.h>
#include <cstdint>

#define NF 128
#define NH 64
#define MAXN 50000
#define MAXE 800000

// Scratch (allocation-free rule: __device__ globals)
__device__ float g_z[(size_t)MAXN * NH];   // 12.8 MB
__device__ float g_sd[MAXN];
__device__ float g_ss[MAXN];
__device__ int   g_dst[MAXE];
__device__ int   g_src[MAXE];
__device__ int   g_cnt[MAXN];
__device__ int   g_rowstart[MAXN];
__device__ int   g_cursor[MAXN];
__device__ int   g_bsum[1024];
__device__ int4  g_csr[MAXE];              // {src, eidx, h_bits, 0}
__device__ int   g_is32;

// ---------------------------------------------------------------------------
__global__ void zero_kernel(int n_nodes) {
    int i = blockIdx.x * blockDim.x + threadIdx.x;
    if (i < n_nodes) g_cnt[i] = 0;
    if (i == 0) g_is32 = 0;
}

__global__ void detect_kernel(const int* __restrict__ w, int nelem) {
    int stride = gridDim.x * blockDim.x;
    int found = 0;
    for (int i = blockIdx.x * blockDim.x + threadIdx.x; i < nelem / 2; i += stride)
        found |= w[2 * i + 1];
    if (found) g_is32 = 1;
}

__global__ void convert_kernel(const void* __restrict__ ei, int E) {
    int i = blockIdx.x * blockDim.x + threadIdx.x;
    if (i >= E) return;
    int d, s;
    if (g_is32) {
        const int* p = (const int*)ei;
        d = p[i]; s = p[E + i];
    } else {
        const long long* p = (const long long*)ei;
        d = (int)p[i]; s = (int)p[E + i];
    }
    g_dst[i] = d;
    g_src[i] = s;
    atomicAdd(&g_cnt[d], 1);
}

// ---------------------------------------------------------------------------
// Exclusive scan of g_cnt -> g_rowstart.
__global__ void scanA(int n) {
    __shared__ int s[256];
    int t = threadIdx.x, i = blockIdx.x * 256 + t;
    s[t] = (i < n) ? g_cnt[i] : 0;
    __syncthreads();
    for (int off = 128; off; off >>= 1) {
        if (t < off) s[t] += s[t + off];
        __syncthreads();
    }
    if (t == 0) g_bsum[blockIdx.x] = s[0];
}

__global__ void scanB(int nb) {
    __shared__ int s[256];
    int t = threadIdx.x;
    int v = (t < nb) ? g_bsum[t] : 0;
    s[t] = v; __syncthreads();
    for (int off = 1; off < 256; off <<= 1) {
        int a = (t >= off) ? s[t - off] : 0;
        __syncthreads();
        s[t] += a;
        __syncthreads();
    }
    if (t < nb) g_bsum[t] = s[t] - v;
}

__global__ void scanC(int n) {
    __shared__ int s[256];
    int t = threadIdx.x, i = blockIdx.x * 256 + t;
    int v = (i < n) ? g_cnt[i] : 0;
    s[t] = v; __syncthreads();
    for (int off = 1; off < 256; off <<= 1) {
        int a = (t >= off) ? s[t - off] : 0;
        __syncthreads();
        s[t] += a;
        __syncthreads();
    }
    if (i < n) {
        int start = g_bsum[blockIdx.x] + s[t] - v;
        g_rowstart[i] = start;
        g_cursor[i]   = start;
    }
}

// ---------------------------------------------------------------------------
// 3xTF32 tensor-core GEMM: z = x @ W, fused s_dst/s_src score reduction.
// Block tile: 128 rows x 64 cols, full K=128 resident. Operands pre-swizzled
// into m16n8k8 fragment order in smem (conflict-free LDS.128 / LDS.64).
#define KSTEPS 16
#define NTILES 8
// smem float offsets
#define WHI_OFF 0
#define WLO_OFF 8192
#define XHI_OFF 16384
#define XLO_OFF 32768
#define SMEM_FLOATS 49152   // 192 KB

__device__ __forceinline__ float tf32_rna(float x) {
    unsigned r;
    asm("cvt.rna.tf32.f32 %0, %1;" : "=r"(r) : "f"(x));
    return __uint_as_float(r);
}

__device__ __forceinline__ void mma_tf32(float* c, float4 a, float2 b) {
    asm volatile(
        "mma.sync.aligned.m16n8k8.row.col.f32.tf32.tf32.f32 "
        "{%0,%1,%2,%3}, {%4,%5,%6,%7}, {%8,%9}, {%0,%1,%2,%3};"
        : "+f"(c[0]), "+f"(c[1]), "+f"(c[2]), "+f"(c[3])
        : "r"(__float_as_uint(a.x)), "r"(__float_as_uint(a.y)),
          "r"(__float_as_uint(a.z)), "r"(__float_as_uint(a.w)),
          "r"(__float_as_uint(b.x)), "r"(__float_as_uint(b.y)));
}

__global__ void __launch_bounds__(256) gemm_tc_kernel(
    const float* __restrict__ x, const float* __restrict__ W,
    const float* __restrict__ aw, int n_nodes)
{
    extern __shared__ float sm[];
    const int tid  = threadIdx.x;
    const int row0 = blockIdx.x * 128;

    // --- W into fragment order (hi/lo) ---
    for (int i = tid; i < NF * NH; i += 256) {
        int k = i >> 6, n = i & 63;
        float v  = W[i];
        float hi = tf32_rna(v);
        float lo = v - hi;
        int kstep = k >> 3, kk = k & 7;
        int lane  = (n & 7) * 4 + (kk & 3);
        int vi    = kk >> 2;                    // b0 / b1
        int ntile = n >> 3;
        int idx = ((kstep * NTILES + ntile) * 32 + lane) * 2 + vi;
        sm[WHI_OFF + idx] = hi;
        sm[WLO_OFF + idx] = lo;
    }

    // --- x tile into fragment order (hi/lo): 128 rows x 128 k ---
    for (int i = tid; i < 128 * 32; i += 256) {
        int r = i >> 5;
        int q = (i & 31) << 2;
        int row = row0 + r;
        float4 v = make_float4(0.f, 0.f, 0.f, 0.f);
        if (row < n_nodes)
            v = *reinterpret_cast<const float4*>(&x[(size_t)row * NF + q]);
        int w  = r >> 4, rr = r & 15;
#pragma unroll
        for (int j = 0; j < 4; j++) {
            float val = (&v.x)[j];
            int k = q + j;
            int kstep = k >> 3, kk = k & 7;
            int lane = (rr & 7) * 4 + (kk & 3);
            int vi   = (kk >> 2) * 2 + (rr >> 3);   // a0..a3
            float hi = tf32_rna(val);
            float lo = val - hi;
            int idx = ((w * KSTEPS + kstep) * 32 + lane) * 4 + vi;
            sm[XHI_OFF + idx] = hi;
            sm[XLO_OFF + idx] = lo;
        }
    }
    __syncthreads();

    const int warp = tid >> 5;
    const int lane = tid & 31;

    float c[NTILES][4];
#pragma unroll
    for (int nt = 0; nt < NTILES; nt++)
#pragma unroll
        for (int j = 0; j < 4; j++) c[nt][j] = 0.f;

#pragma unroll 4
    for (int ks = 0; ks < KSTEPS; ks++) {
        int abase = ((warp * KSTEPS + ks) * 32 + lane) * 4;
        float4 ah = *reinterpret_cast<const float4*>(&sm[XHI_OFF + abase]);
        float4 al = *reinterpret_cast<const float4*>(&sm[XLO_OFF + abase]);
#pragma unroll
        for (int nt = 0; nt < NTILES; nt++) {
            int bbase = ((ks * NTILES + nt) * 32 + lane) * 2;
            float2 bh = *reinterpret_cast<const float2*>(&sm[WHI_OFF + bbase]);
            float2 bl = *reinterpret_cast<const float2*>(&sm[WLO_OFF + bbase]);
            mma_tf32(c[nt], ah, bh);
            mma_tf32(c[nt], al, bh);
            mma_tf32(c[nt], ah, bl);
        }
    }

    // --- epilogue: write z + fused score reduction ---
    const int g = lane >> 2;
    const int t = lane & 3;
    const int row_a = row0 + warp * 16 + g;
    const int row_b = row_a + 8;

    float sdA = 0.f, ssA = 0.f, sdB = 0.f, ssB = 0.f;
#pragma unroll
    for (int nt = 0; nt < NTILES; nt++) {
        int col = nt * 8 + 2 * t;
        float a1x = __ldg(&aw[col]),      a1y = __ldg(&aw[col + 1]);
        float a2x = __ldg(&aw[NH + col]), a2y = __ldg(&aw[NH + col + 1]);
        sdA += c[nt][0] * a1x + c[nt][1] * a1y;
        ssA += c[nt][0] * a2x + c[nt][1] * a2y;
        sdB += c[nt][2] * a1x + c[nt][3] * a1y;
        ssB += c[nt][2] * a2x + c[nt][3] * a2y;
    }
#pragma unroll
    for (int off = 2; off; off >>= 1) {
        sdA += __shfl_down_sync(0xffffffffu, sdA, off, 4);
        ssA += __shfl_down_sync(0xffffffffu, ssA, off, 4);
        sdB += __shfl_down_sync(0xffffffffu, sdB, off, 4);
        ssB += __shfl_down_sync(0xffffffffu, ssB, off, 4);
    }

    if (row_a < n_nodes) {
#pragma unroll
        for (int nt = 0; nt < NTILES; nt++)
            *reinterpret_cast<float2*>(&g_z[(size_t)row_a * NH + nt * 8 + 2 * t]) =
                make_float2(c[nt][0], c[nt][1]);
        if (t == 0) { g_sd[row_a] = sdA; g_ss[row_a] = ssA; }
    }
    if (row_b < n_nodes) {
#pragma unroll
        for (int nt = 0; nt < NTILES; nt++)
            *reinterpret_cast<float2*>(&g_z[(size_t)row_b * NH + nt * 8 + 2 * t]) =
                make_float2(c[nt][2], c[nt][3]);
        if (t == 0) { g_sd[row_b] = sdB; g_ss[row_b] = ssB; }
    }
}

// ---------------------------------------------------------------------------
__global__ void edge_scatter_kernel(const float* __restrict__ ab, int E) {
    int e = blockIdx.x * blockDim.x + threadIdx.x;
    if (e >= E) return;
    int d = g_dst[e], s = g_src[e];
    float h = g_sd[d] + g_ss[s] + __ldg(ab);
    h = (h >= 0.f) ? h : 0.05f * h;
    h = expf(h);
    int pos = atomicAdd(&g_cursor[d], 1);
    g_csr[pos] = make_int4(s, e, __float_as_int(h), 0);
}

// ---------------------------------------------------------------------------
__global__ void __launch_bounds__(256) aggregate_csr_kernel(
    float* __restrict__ out, float* __restrict__ alpha, int n_nodes)
{
    int w = (blockIdx.x * 256 + threadIdx.x) >> 5;
    int lane = threadIdx.x & 31;
    if (w >= n_nodes) return;

    int start = g_rowstart[w];
    int deg   = g_cnt[w];

    float2 acc = make_float2(0.f, 0.f);
    float hs = 0.f;
    for (int e = 0; e < deg; e++) {
        int4 ent = g_csr[start + e];
        float h = __int_as_float(ent.z);
        hs += h;
        float2 zv = *reinterpret_cast<const float2*>(
            &g_z[(size_t)ent.x * NH + lane * 2]);
        acc.x = fmaf(h, zv.x, acc.x);
        acc.y = fmaf(h, zv.y, acc.y);
    }
    float inv = (hs != 0.f) ? (1.f / hs) : 0.f;
    *reinterpret_cast<float2*>(&out[(size_t)w * NH + lane * 2]) =
        make_float2(acc.x * inv, acc.y * inv);

    for (int e = lane; e < deg; e += 32) {
        int4 ent = g_csr[start + e];
        alpha[ent.y] = __int_as_float(ent.z) * inv;
    }
}

// ---------------------------------------------------------------------------
extern "C" void kernel_launch(void* const* d_in, const int* in_sizes, int n_in,
                              void* d_out, int out_size)
{
    const float* x  = (const float*)d_in[0];
    const void*  ei = d_in[1];
    const float* W  = (const float*)d_in[2];
    const float* aw = (const float*)d_in[3];
    const float* ab = (const float*)d_in[4];

    const int n_nodes = in_sizes[0] / NF;
    const int E       = in_sizes[1] / 2;
    const int nb      = (n_nodes + 255) / 256;

    float* out   = (float*)d_out;
    float* alpha = out + (size_t)n_nodes * NH;

    static int smem_set = 0;
    if (!smem_set) {
        cudaFuncSetAttribute(gemm_tc_kernel,
                             cudaFuncAttributeMaxDynamicSharedMemorySize,
                             SMEM_FLOATS * sizeof(float));
        smem_set = 1;
    }

    zero_kernel<<<(n_nodes + 1023) / 1024, 1024>>>(n_nodes);
    detect_kernel<<<256, 256>>>((const int*)ei, in_sizes[1]);
    convert_kernel<<<(E + 255) / 256, 256>>>(ei, E);

    gemm_tc_kernel<<<(n_nodes + 127) / 128, 256,
                     SMEM_FLOATS * sizeof(float)>>>(x, W, aw, n_nodes);

    scanA<<<nb, 256>>>(n_nodes);
    scanB<<<1, 256>>>(nb);
    scanC<<<nb, 256>>>(n_nodes);

    edge_scatter_kernel<<<(E + 255) / 256, 256>>>(ab, E);

    long long tot = (long long)n_nodes * 32;
    aggregate_csr_kernel<<<(int)((tot + 255) / 256), 256>>>(out, alpha, n_nodes);
}

// round 6
// speedup vs baseline: 1.2464x; 1.2464x over previous
#include <cuda_runtime.h>
#include <cstdint>

#define NF 128
#define NH 64
#define MAXN 50000
#define MAXE 800000

// Scratch (allocation-free rule: __device__ globals)
__device__ float g_z[(size_t)MAXN * NH];   // 12.8 MB
__device__ float g_sd[MAXN];
__device__ float g_ss[MAXN];
__device__ int   g_dst[MAXE];
__device__ int   g_src[MAXE];
__device__ int   g_cnt[MAXN];
__device__ int   g_rowstart[MAXN];
__device__ int   g_cursor[MAXN];
__device__ int   g_bsum[1024];
__device__ int4  g_csr[MAXE];              // {src, eidx, h_bits, 0}
__device__ int   g_is32;

// ---------------------------------------------------------------------------
__global__ void zero_kernel(int n_nodes) {
    int i = blockIdx.x * blockDim.x + threadIdx.x;
    if (i < n_nodes) g_cnt[i] = 0;
    if (i == 0) g_is32 = 0;
}

__global__ void detect_kernel(const int* __restrict__ w, int nelem) {
    int stride = gridDim.x * blockDim.x;
    int found = 0;
    for (int i = blockIdx.x * blockDim.x + threadIdx.x; i < nelem / 2; i += stride)
        found |= w[2 * i + 1];
    if (found) g_is32 = 1;
}

__global__ void convert_kernel(const void* __restrict__ ei, int E) {
    int i = blockIdx.x * blockDim.x + threadIdx.x;
    if (i >= E) return;
    int d, s;
    if (g_is32) {
        const int* p = (const int*)ei;
        d = p[i]; s = p[E + i];
    } else {
        const long long* p = (const long long*)ei;
        d = (int)p[i]; s = (int)p[E + i];
    }
    g_dst[i] = d;
    g_src[i] = s;
    atomicAdd(&g_cnt[d], 1);
}

// ---------------------------------------------------------------------------
// Exclusive scan of g_cnt -> g_rowstart.
__global__ void scanA(int n) {
    __shared__ int s[256];
    int t = threadIdx.x, i = blockIdx.x * 256 + t;
    s[t] = (i < n) ? g_cnt[i] : 0;
    __syncthreads();
    for (int off = 128; off; off >>= 1) {
        if (t < off) s[t] += s[t + off];
        __syncthreads();
    }
    if (t == 0) g_bsum[blockIdx.x] = s[0];
}

__global__ void scanB(int nb) {
    __shared__ int s[256];
    int t = threadIdx.x;
    int v = (t < nb) ? g_bsum[t] : 0;
    s[t] = v; __syncthreads();
    for (int off = 1; off < 256; off <<= 1) {
        int a = (t >= off) ? s[t - off] : 0;
        __syncthreads();
        s[t] += a;
        __syncthreads();
    }
    if (t < nb) g_bsum[t] = s[t] - v;
}

__global__ void scanC(int n) {
    __shared__ int s[256];
    int t = threadIdx.x, i = blockIdx.x * 256 + t;
    int v = (i < n) ? g_cnt[i] : 0;
    s[t] = v; __syncthreads();
    for (int off = 1; off < 256; off <<= 1) {
        int a = (t >= off) ? s[t - off] : 0;
        __syncthreads();
        s[t] += a;
        __syncthreads();
    }
    if (i < n) {
        int start = g_bsum[blockIdx.x] + s[t] - v;
        g_rowstart[i] = start;
        g_cursor[i]   = start;
    }
}

// ---------------------------------------------------------------------------
// 3xTF32 tensor-core GEMM v2: plain padded row-major smem operands,
// hi/lo split computed in registers, fragments loaded conflict-free.
// smem: W [128][68] (34.8 KB) + x [128][132] (67.6 KB) = 100 KB -> 2 CTA/SM.
#define W_STRIDE 68
#define X_STRIDE 132
#define W_FLOATS (NF * W_STRIDE)
#define SMEM_FLOATS (W_FLOATS + 128 * X_STRIDE)
#define NTILES 8

__device__ __forceinline__ float tf32_rna(float x) {
    unsigned r;
    asm("cvt.rna.tf32.f32 %0, %1;" : "=r"(r) : "f"(x));
    return __uint_as_float(r);
}

__device__ __forceinline__ void mma_tf32(float* c, float4 a, float2 b) {
    asm volatile(
        "mma.sync.aligned.m16n8k8.row.col.f32.tf32.tf32.f32 "
        "{%0,%1,%2,%3}, {%4,%5,%6,%7}, {%8,%9}, {%0,%1,%2,%3};"
        : "+f"(c[0]), "+f"(c[1]), "+f"(c[2]), "+f"(c[3])
        : "r"(__float_as_uint(a.x)), "r"(__float_as_uint(a.y)),
          "r"(__float_as_uint(a.z)), "r"(__float_as_uint(a.w)),
          "r"(__float_as_uint(b.x)), "r"(__float_as_uint(b.y)));
}

__global__ void __launch_bounds__(256, 2) gemm_tc_kernel(
    const float* __restrict__ x, const float* __restrict__ W,
    const float* __restrict__ aw, int n_nodes)
{
    extern __shared__ float sm[];
    float* wsm = sm;              // [128][68]
    float* xsm = sm + W_FLOATS;   // [128][132]

    const int tid  = threadIdx.x;
    const int row0 = blockIdx.x * 128;

    // --- W copy (coalesced float4, row-major padded) ---
    for (int i = tid; i < NF * NH / 4; i += 256) {
        int k = i >> 4, n = (i & 15) << 2;
        float4 v = *reinterpret_cast<const float4*>(&W[(size_t)k * NH + n]);
        *reinterpret_cast<float4*>(&wsm[k * W_STRIDE + n]) = v;
    }
    // --- x tile copy (coalesced float4, row-major padded) ---
    for (int i = tid; i < 128 * 32; i += 256) {
        int r = i >> 5, q = (i & 31) << 2;
        int row = row0 + r;
        float4 v = make_float4(0.f, 0.f, 0.f, 0.f);
        if (row < n_nodes)
            v = *reinterpret_cast<const float4*>(&x[(size_t)row * NF + q]);
        *reinterpret_cast<float4*>(&xsm[r * X_STRIDE + q]) = v;
    }
    __syncthreads();

    const int warp = tid >> 5;
    const int lane = tid & 31;
    const int g = lane >> 2;
    const int t = lane & 3;

    float c[NTILES][4];
#pragma unroll
    for (int nt = 0; nt < NTILES; nt++)
#pragma unroll
        for (int j = 0; j < 4; j++) c[nt][j] = 0.f;

    const float* xrowA = &xsm[(warp * 16 + g) * X_STRIDE];       // row g
    const float* xrowB = xrowA + 8 * X_STRIDE;                   // row g+8

#pragma unroll
    for (int ks = 0; ks < 16; ks++) {
        int k0 = ks * 8 + t;
        // A fragment (conflict-free: bank = 4g+t permutation)
        float a0f = xrowA[k0];
        float a1f = xrowB[k0];
        float a2f = xrowA[k0 + 4];
        float a3f = xrowB[k0 + 4];
        float4 ah = make_float4(tf32_rna(a0f), tf32_rna(a1f),
                                tf32_rna(a2f), tf32_rna(a3f));
        float4 al = make_float4(a0f - ah.x, a1f - ah.y,
                                a2f - ah.z, a3f - ah.w);
        const float* wrow0 = &wsm[k0 * W_STRIDE + g];
        const float* wrow1 = wrow0 + 4 * W_STRIDE;
#pragma unroll
        for (int nt = 0; nt < NTILES; nt++) {
            float b0f = wrow0[nt * 8];
            float b1f = wrow1[nt * 8];
            float2 bh = make_float2(tf32_rna(b0f), tf32_rna(b1f));
            float2 bl = make_float2(b0f - bh.x, b1f - bh.y);
            mma_tf32(c[nt], ah, bh);
            mma_tf32(c[nt], al, bh);
            mma_tf32(c[nt], ah, bl);
        }
    }

    // --- epilogue: write z + fused score reduction ---
    const int row_a = row0 + warp * 16 + g;
    const int row_b = row_a + 8;

    float sdA = 0.f, ssA = 0.f, sdB = 0.f, ssB = 0.f;
#pragma unroll
    for (int nt = 0; nt < NTILES; nt++) {
        int col = nt * 8 + 2 * t;
        float a1x = __ldg(&aw[col]),      a1y = __ldg(&aw[col + 1]);
        float a2x = __ldg(&aw[NH + col]), a2y = __ldg(&aw[NH + col + 1]);
        sdA += c[nt][0] * a1x + c[nt][1] * a1y;
        ssA += c[nt][0] * a2x + c[nt][1] * a2y;
        sdB += c[nt][2] * a1x + c[nt][3] * a1y;
        ssB += c[nt][2] * a2x + c[nt][3] * a2y;
    }
#pragma unroll
    for (int off = 2; off; off >>= 1) {
        sdA += __shfl_down_sync(0xffffffffu, sdA, off, 4);
        ssA += __shfl_down_sync(0xffffffffu, ssA, off, 4);
        sdB += __shfl_down_sync(0xffffffffu, sdB, off, 4);
        ssB += __shfl_down_sync(0xffffffffu, ssB, off, 4);
    }

    if (row_a < n_nodes) {
#pragma unroll
        for (int nt = 0; nt < NTILES; nt++)
            *reinterpret_cast<float2*>(&g_z[(size_t)row_a * NH + nt * 8 + 2 * t]) =
                make_float2(c[nt][0], c[nt][1]);
        if (t == 0) { g_sd[row_a] = sdA; g_ss[row_a] = ssA; }
    }
    if (row_b < n_nodes) {
#pragma unroll
        for (int nt = 0; nt < NTILES; nt++)
            *reinterpret_cast<float2*>(&g_z[(size_t)row_b * NH + nt * 8 + 2 * t]) =
                make_float2(c[nt][2], c[nt][3]);
        if (t == 0) { g_sd[row_b] = sdB; g_ss[row_b] = ssB; }
    }
}

// ---------------------------------------------------------------------------
__global__ void edge_scatter_kernel(const float* __restrict__ ab, int E) {
    int e = blockIdx.x * blockDim.x + threadIdx.x;
    if (e >= E) return;
    int d = g_dst[e], s = g_src[e];
    float h = g_sd[d] + g_ss[s] + __ldg(ab);
    h = (h >= 0.f) ? h : 0.05f * h;
    h = expf(h);
    int pos = atomicAdd(&g_cursor[d], 1);
    g_csr[pos] = make_int4(s, e, __float_as_int(h), 0);
}

// ---------------------------------------------------------------------------
__global__ void __launch_bounds__(256) aggregate_csr_kernel(
    float* __restrict__ out, float* __restrict__ alpha, int n_nodes)
{
    int w = (blockIdx.x * 256 + threadIdx.x) >> 5;
    int lane = threadIdx.x & 31;
    if (w >= n_nodes) return;

    int start = g_rowstart[w];
    int deg   = g_cnt[w];

    float2 acc = make_float2(0.f, 0.f);
    float hs = 0.f;
    for (int e = 0; e < deg; e++) {
        int4 ent = g_csr[start + e];
        float h = __int_as_float(ent.z);
        hs += h;
        float2 zv = *reinterpret_cast<const float2*>(
            &g_z[(size_t)ent.x * NH + lane * 2]);
        acc.x = fmaf(h, zv.x, acc.x);
        acc.y = fmaf(h, zv.y, acc.y);
    }
    float inv = (hs != 0.f) ? (1.f / hs) : 0.f;
    *reinterpret_cast<float2*>(&out[(size_t)w * NH + lane * 2]) =
        make_float2(acc.x * inv, acc.y * inv);

    for (int e = lane; e < deg; e += 32) {
        int4 ent = g_csr[start + e];
        alpha[ent.y] = __int_as_float(ent.z) * inv;
    }
}

// ---------------------------------------------------------------------------
extern "C" void kernel_launch(void* const* d_in, const int* in_sizes, int n_in,
                              void* d_out, int out_size)
{
    const float* x  = (const float*)d_in[0];
    const void*  ei = d_in[1];
    const float* W  = (const float*)d_in[2];
    const float* aw = (const float*)d_in[3];
    const float* ab = (const float*)d_in[4];

    const int n_nodes = in_sizes[0] / NF;
    const int E       = in_sizes[1] / 2;
    const int nb      = (n_nodes + 255) / 256;

    float* out   = (float*)d_out;
    float* alpha = out + (size_t)n_nodes * NH;

    static int smem_set = 0;
    if (!smem_set) {
        cudaFuncSetAttribute(gemm_tc_kernel,
                             cudaFuncAttributeMaxDynamicSharedMemorySize,
                             SMEM_FLOATS * sizeof(float));
        smem_set = 1;
    }

    zero_kernel<<<(n_nodes + 1023) / 1024, 1024>>>(n_nodes);
    detect_kernel<<<256, 256>>>((const int*)ei, in_sizes[1]);
    convert_kernel<<<(E + 255) / 256, 256>>>(ei, E);

    gemm_tc_kernel<<<(n_nodes + 127) / 128, 256,
                     SMEM_FLOATS * sizeof(float)>>>(x, W, aw, n_nodes);

    scanA<<<nb, 256>>>(n_nodes);
    scanB<<<1, 256>>>(nb);
    scanC<<<nb, 256>>>(n_nodes);

    edge_scatter_kernel<<<(E + 255) / 256, 256>>>(ab, E);

    long long tot = (long long)n_nodes * 32;
    aggregate_csr_kernel<<<(int)((tot + 255) / 256), 256>>>(out, alpha, n_nodes);
}